// round 10
// baseline (speedup 1.0000x reference)
#include <cuda_runtime.h>
#include <cuda_bf16.h>

// Problem constants (fixed by the dataset: b=2, c=8, h=w=128, P=3, Wn=7)
#define IMG_H 128
#define IMG_W 128
#define NCH 8
#define NB 2
#define PL (IMG_H*IMG_W)

#define TY 8
#define TX 16
#define NPIX (TY*TX)           // 128 pixels per tile
#define NSLICE 4
#define NTHREADS (NPIX*NSLICE) // 512
#define HP 4                   // phi halo
#define HG 3                   // g halo
#define PH (TY + 2*HP)         // 16
#define PW (TX + 2*HP)         // 24
#define GH (TY + 2*HG)         // 14
#define GW (TX + 2*HG)         // 22
#define NPHI (PH*PW)           // 384
#define NG (GH*GW)             // 308

#define CW 18
#define CHh 10
#define CN (CHh*CW)            // 180
#define CNP 184
#define KMAX 13                // maps per slice (slice 0: 13, others: 12)

#define HW 16
#define HN (CHh*HW)            // 160
#define HPAIRS (CHh*HW/2)      // 80
#define HUNITS (KMAX*HPAIRS)   // 1040

// ---- dynamic shared memory layout (bytes) ----
#define OFF_PHIA 0
#define OFF_PHIB (OFF_PHIA + NPHI*16)
#define OFF_GA   (OFF_PHIB + NPHI*16)
#define OFF_GB   (OFF_GA   + NG*16)
#define OFF_CS   (OFF_GB   + NG*16)
#define OFF_WPHI (OFF_CS   + NSLICE*KMAX*CNP*4)
#define OFF_WG   (OFF_WPHI + 256)
#define OFF_HS   (OFF_WG   + 256)
#define SMEM_TOTAL (OFF_HS + NSLICE*KMAX*HN*4)   // 94208

#define BARS(id) asm volatile("bar.sync %0, %1;" :: "r"(id), "r"(128) : "memory")

#define MUL2(out, a, b) \
    asm("mul.rn.f32x2 %0, %1, %2;" : "=l"(out) : "l"(a), "l"(b))
#define FMA2(out, a, b, c) \
    asm("fma.rn.f32x2 %0, %1, %2, %3;" : "=l"(out) : "l"(a), "l"(b), "l"(c))
#define PACK2(out, lo, hi) \
    asm("mov.b64 %0, {%1, %2};" : "=l"(out) : "f"(lo), "f"(hi))
#define UNPACK2(lo, hi, in) \
    asm("mov.b64 {%0, %1}, %2;" : "=f"(lo), "=f"(hi) : "l"(in))

// compile-time per-offset table: {phi-desc offset, g offset, dy, dx}
#define JT4(j) { ((j)/7-3)*PW + ((j)%7-3), ((j)/7)*GW + ((j)%7), (j)/7-3, (j)%7-3 }
__constant__ int4 JT[49] = {
    JT4(0),  JT4(1),  JT4(2),  JT4(3),  JT4(4),  JT4(5),  JT4(6),
    JT4(7),  JT4(8),  JT4(9),  JT4(10), JT4(11), JT4(12), JT4(13),
    JT4(14), JT4(15), JT4(16), JT4(17), JT4(18), JT4(19), JT4(20),
    JT4(21), JT4(22), JT4(23), JT4(24), JT4(25), JT4(26), JT4(27),
    JT4(28), JT4(29), JT4(30), JT4(31), JT4(32), JT4(33), JT4(34),
    JT4(35), JT4(36), JT4(37), JT4(38), JT4(39), JT4(40), JT4(41),
    JT4(42), JT4(43), JT4(44), JT4(45), JT4(46), JT4(47), JT4(48)
};

// FMA-pipe exp, input clamped at -80 (only hits weights <= e^-50 of max term).
__device__ __forceinline__ float fexp(float x)
{
    float y = fmaxf(x, -80.f) * 1.44269504f;
    float r = y + 12582912.f;
    int   n = __float_as_int(r) - 0x4B400000;
    float f = y - (r - 12582912.f);
    float p =              0.00961813f;
    p = __fmaf_rn(p, f,    0.05550411f);
    p = __fmaf_rn(p, f,    0.24022651f);
    p = __fmaf_rn(p, f,    0.69314718f);
    p = __fmaf_rn(p, f,    1.0f);
    return __int_as_float(__float_as_int(p) + (n << 23));
}

__global__ __launch_bounds__(NTHREADS, 2)
void attn_bal_kernel(const float* __restrict__ u,
                     const float* __restrict__ pan,
                     const float* __restrict__ Wphi,
                     const float* __restrict__ Wg,
                     float* __restrict__ out)
{
    extern __shared__ __align__(16) char smem_raw[];
    float4* phiA = (float4*)(smem_raw + OFF_PHIA);
    float4* phiB = (float4*)(smem_raw + OFF_PHIB);
    float4* gA   = (float4*)(smem_raw + OFF_GA);
    float4* gB   = (float4*)(smem_raw + OFF_GB);
    float*  Csb  = (float*)(smem_raw + OFF_CS);
    float*  wphi_s = (float*)(smem_raw + OFF_WPHI);
    float*  wg_s   = (float*)(smem_raw + OFF_WG);
    float*  Hsb  = (float*)(smem_raw + OFF_HS);

    const int tid  = threadIdx.x;
    const int bimg = blockIdx.z;
    const int y0   = blockIdx.y * TY;
    const int x0   = blockIdx.x * TX;

    const float* panb = pan + (size_t)bimg * NCH * PL;
    const float* ub   = u   + (size_t)bimg * NCH * PL;

    // ---- prologue: issue input LDGs FIRST (in flight across the weight sync) ----
    const bool doPhi = (tid < NPHI);
    const int  gcell = (tid >= NPHI) ? (tid - NPHI)
                     : (tid < NG - NPIX ? tid + NPIX : -1);

    float pv[NCH], uv[NCH];
    if (doPhi) {
        int r = tid / PW, c = tid % PW;
        int yy = y0 - HP + r, xx = x0 - HP + c;
        bool in = ((unsigned)yy < IMG_H) && ((unsigned)xx < IMG_W);
        #pragma unroll
        for (int ch = 0; ch < NCH; ch++)
            pv[ch] = in ? panb[ch*PL + yy*IMG_W + xx] : 0.f;
    }
    if (gcell >= 0) {
        int r = gcell / GW, c = gcell % GW;
        int yy = y0 - HG + r, xx = x0 - HG + c;
        bool in = ((unsigned)yy < IMG_H) && ((unsigned)xx < IMG_W);
        #pragma unroll
        for (int ch = 0; ch < NCH; ch++)
            uv[ch] = in ? ub[ch*PL + yy*IMG_W + xx] : 0.f;
    }

    if (tid < NCH*NCH)              wphi_s[tid] = Wphi[tid];
    else if (tid < 2*NCH*NCH)       wg_s[tid - NCH*NCH] = Wg[tid - NCH*NCH];
    __syncthreads();

    if (doPhi) {
        float po[NCH];
        #pragma unroll
        for (int o = 0; o < NCH; o++) {
            float acc = 0.f;
            #pragma unroll
            for (int ci = 0; ci < NCH; ci++)
                acc = fmaf(wphi_s[o*NCH+ci], pv[ci], acc);
            po[o] = acc;
        }
        phiA[tid] = make_float4(po[0], po[1], po[2], po[3]);
        phiB[tid] = make_float4(po[4], po[5], po[6], po[7]);
    }
    if (gcell >= 0) {
        float go[NCH];
        #pragma unroll
        for (int o = 0; o < NCH; o++) {
            float acc = 0.f;
            #pragma unroll
            for (int ci = 0; ci < NCH; ci++)
                acc = fmaf(wg_s[o*NCH+ci], uv[ci], acc);
            go[o] = acc;
        }
        gA[gcell] = make_float4(go[0], go[1], go[2], go[3]);
        gB[gcell] = make_float4(go[4], go[5], go[6], go[7]);
    }
    __syncthreads();

    const int px    = tid & (NPIX-1);
    const int slice = tid >> 7;            // owns offsets j = slice + 4k
    const int bar   = slice + 1;
    const int ty = px / TX, tx = px % TX;
    const int gy = y0 + ty, gx = x0 + tx;

    // primary correlation position = px; extra positions spread evenly:
    // each warp's lanes 0..12 take p1 = 128 + warp*13 + lane  (covers 128..179)
    const int p0    = px;
    const int cell0 = (p0/CW + 3) * PW + (p0%CW + 3);
    const int lane  = px & 31;
    const bool has1 = (lane < 13);
    const int p1    = NPIX + (px >> 5) * 13 + lane;  // 128..179 when has1
    const int cell1 = has1 ? (p1/CW + 3) * PW + (p1%CW + 3) : cell0;

    unsigned long long v0p0, v0p1, v0p2, v0p3, v1p0, v1p1, v1p2, v1p3;
    {
        ulonglong2 a = *(const ulonglong2*)&phiA[cell0];
        ulonglong2 b = *(const ulonglong2*)&phiB[cell0];
        v0p0 = a.x; v0p1 = a.y; v0p2 = b.x; v0p3 = b.y;
        ulonglong2 a1 = *(const ulonglong2*)&phiA[cell1];
        ulonglong2 b1 = *(const ulonglong2*)&phiB[cell1];
        v1p0 = a1.x; v1p1 = a1.y; v1p2 = b1.x; v1p3 = b1.y;
    }

    float* Cme = Csb + slice * (KMAX*CNP);
    float* Hme = Hsb + slice * (KMAX*HN);

    // ---- produce all C maps for this slice (balanced across warps) ----
    #pragma unroll
    for (int k = 0; k < KMAX; k++) {
        const int j = slice + 4*k;
        if (j < 49) {
            const int off = JT[j].x;
            {
                ulonglong2 wa = *(const ulonglong2*)&phiA[cell0 + off];
                ulonglong2 wb = *(const ulonglong2*)&phiB[cell0 + off];
                unsigned long long acc;
                MUL2(acc, v0p0, wa.x);
                FMA2(acc, v0p1, wa.y, acc);
                FMA2(acc, v0p2, wb.x, acc);
                FMA2(acc, v0p3, wb.y, acc);
                float lo, hi; UNPACK2(lo, hi, acc);
                Cme[k*CNP + p0] = lo + hi;
            }
            if (has1) {
                ulonglong2 wa = *(const ulonglong2*)&phiA[cell1 + off];
                ulonglong2 wb = *(const ulonglong2*)&phiB[cell1 + off];
                unsigned long long acc;
                MUL2(acc, v1p0, wa.x);
                FMA2(acc, v1p1, wa.y, acc);
                FMA2(acc, v1p2, wb.x, acc);
                FMA2(acc, v1p3, wb.y, acc);
                float lo, hi; UNPACK2(lo, hi, acc);
                Cme[k*CNP + p1] = lo + hi;
            }
        }
    }
    BARS(bar);     // slice-local: C produce -> H stage

    // ---- H stage: horizontal 3-sums, pairs of columns ----
    #pragma unroll
    for (int i = 0; i < 9; i++) {
        const int uu = px + 128*i;
        if (uu < HUNITS) {
            const int k  = uu / HPAIRS;
            const int pr = uu - k*HPAIRS;
            const int r  = pr >> 3;
            const int c0 = (pr & 7) << 1;
            const float2 a = *(const float2*)&Cme[k*CNP + r*CW + c0];
            const float2 b = *(const float2*)&Cme[k*CNP + r*CW + c0 + 2];
            float h0 = a.x + a.y + b.x;
            float h1 = a.y + b.x + b.y;
            *(float2*)&Hme[k*HN + r*HW + c0] = make_float2(h0, h1);
        }
    }
    __syncthreads();   // full: all slices need slice0's H (k=6 <-> j=24, delta=0)

    // ---- per-pixel shift b = self-logit ||theta_q||^2 (box-sum of C_0) ----
    float b;
    {
        const float* h0 = &Hsb[6*HN + ty*HW + tx];
        b = h0[0] + h0[HW] + h0[2*HW];
    }

    // ---- single fused pass: logit -> exp(l-b) -> accumulate ----
    const int gbase = ty * GW + tx;
    float S = 0.f;
    unsigned long long o01 = 0ULL, o23 = 0ULL, o45 = 0ULL, o67 = 0ULL;
    #pragma unroll
    for (int k = 0; k < KMAX; k++) {
        const int j = slice + 4*k;
        if (j < 49) {
            const int4 jt = JT[j];
            const float* hb = &Hme[k*HN + ty*HW + tx];
            float v = hb[0] + hb[HW] + hb[2*HW];
            const bool in = ((unsigned)(gy+jt.z) < IMG_H) && ((unsigned)(gx+jt.w) < IMG_W);
            float l = in ? v : 0.f;       // double-unfold: OOB logit exactly 0
            float e = fexp(l - b);
            S += e;
            unsigned long long e2; PACK2(e2, e, e);
            const int gi = gbase + jt.y;
            ulonglong2 g0 = *(const ulonglong2*)&gA[gi];
            ulonglong2 g1 = *(const ulonglong2*)&gB[gi];
            FMA2(o01, e2, g0.x, o01);
            FMA2(o23, e2, g0.y, o23);
            FMA2(o45, e2, g1.x, o45);
            FMA2(o67, e2, g1.y, o67);
        }
    }

    // ---- merge: plain sums across the 4 slices (common shift b) ----
    __syncthreads();                      // all slices done with Cs/Hs
    float o0,o1,o2,o3,o4,o5,o6,o7;
    UNPACK2(o0,o1,o01); UNPACK2(o2,o3,o23);
    UNPACK2(o4,o5,o45); UNPACK2(o6,o7,o67);
    float* red = Csb;                     // 9*512 = 4608 floats of scratch
    red[tid] = S;
    red[NTHREADS + 0*NTHREADS + tid] = o0;
    red[NTHREADS + 1*NTHREADS + tid] = o1;
    red[NTHREADS + 2*NTHREADS + tid] = o2;
    red[NTHREADS + 3*NTHREADS + tid] = o3;
    red[NTHREADS + 4*NTHREADS + tid] = o4;
    red[NTHREADS + 5*NTHREADS + tid] = o5;
    red[NTHREADS + 6*NTHREADS + tid] = o6;
    red[NTHREADS + 7*NTHREADS + tid] = o7;
    __syncthreads();

    {
        float St = red[0*NPIX + px] + red[1*NPIX + px]
                 + red[2*NPIX + px] + red[3*NPIX + px];
        float inv = 1.f / St;

        const int ch0 = 2*slice;          // each slice writes 2 channels
        float* ob = out + (size_t)bimg*NCH*PL + (size_t)gy*IMG_W + gx;
        #pragma unroll
        for (int cc = 0; cc < 2; cc++) {
            const int ch = ch0 + cc;
            const float* rc = red + NTHREADS + ch*NTHREADS + px;
            float v = rc[0*NPIX] + rc[1*NPIX] + rc[2*NPIX] + rc[3*NPIX];
            ob[ch*PL] = v * inv;
        }
    }
}

extern "C" void kernel_launch(void* const* d_in, const int* in_sizes, int n_in,
                              void* d_out, int out_size)
{
    const float* u    = (const float*)d_in[0];
    const float* pan  = (const float*)d_in[1];
    const float* Wphi = (const float*)d_in[2];
    const float* Wg   = (const float*)d_in[3];
    float* out = (float*)d_out;

    cudaFuncSetAttribute(attn_bal_kernel,
                         cudaFuncAttributeMaxDynamicSharedMemorySize, SMEM_TOTAL);

    dim3 grid(IMG_W / TX, IMG_H / TY, NB);   // (8, 16, 2) = 256 blocks
    dim3 block(NTHREADS);                     // 512
    attn_bal_kernel<<<grid, block, SMEM_TOTAL>>>(u, pan, Wphi, Wg, out);
}

// round 11
// speedup vs baseline: 1.0040x; 1.0040x over previous
#include <cuda_runtime.h>
#include <cuda_bf16.h>

// Problem constants (fixed by the dataset: b=2, c=8, h=w=128, P=3, Wn=7)
#define IMG_H 128
#define IMG_W 128
#define NCH 8
#define NB 2
#define PL (IMG_H*IMG_W)

#define TY 8
#define TX 16
#define NPIX (TY*TX)           // 128 pixels per tile
#define NSLICE 4
#define NTHREADS (NPIX*NSLICE) // 512
#define HP 4                   // phi halo
#define HG 3                   // g halo
#define PH (TY + 2*HP)         // 16
#define PW (TX + 2*HP)         // 24
#define GH (TY + 2*HG)         // 14
#define GW (TX + 2*HG)         // 22
#define NPHI (PH*PW)           // 384
#define NG (GH*GW)             // 308

#define CW 18
#define CHh 10
#define CN (CHh*CW)            // 180
#define CNP 184
#define KMAX 13                // maps per slice (slice 0: 13, others: 12)

#define HW 16
#define HN (CHh*HW)            // 160
#define HPAIRS (CHh*HW/2)      // 80
#define HUNITS (KMAX*HPAIRS)   // 1040

// ---- dynamic shared memory layout (bytes) ----
#define OFF_PHIA 0
#define OFF_PHIB (OFF_PHIA + NPHI*16)
#define OFF_GA   (OFF_PHIB + NPHI*16)
#define OFF_GB   (OFF_GA   + NG*16)
#define OFF_CS   (OFF_GB   + NG*16)
#define OFF_WPK  (OFF_CS   + NSLICE*KMAX*CNP*4)  // packed weights: 2*32 u64
#define OFF_HS   (OFF_WPK  + 512)
#define SMEM_TOTAL (OFF_HS + NSLICE*KMAX*HN*4)   // 94208

#define BARS(id) asm volatile("bar.sync %0, %1;" :: "r"(id), "r"(128) : "memory")

#define MUL2(out, a, b) \
    asm("mul.rn.f32x2 %0, %1, %2;" : "=l"(out) : "l"(a), "l"(b))
#define FMA2(out, a, b, c) \
    asm("fma.rn.f32x2 %0, %1, %2, %3;" : "=l"(out) : "l"(a), "l"(b), "l"(c))
#define PACK2(out, lo, hi) \
    asm("mov.b64 %0, {%1, %2};" : "=l"(out) : "f"(lo), "f"(hi))
#define UNPACK2(lo, hi, in) \
    asm("mov.b64 {%0, %1}, %2;" : "=f"(lo), "=f"(hi) : "l"(in))

// compile-time per-offset table: {phi-desc offset, g offset, dy, dx}
#define JT4(j) { ((j)/7-3)*PW + ((j)%7-3), ((j)/7)*GW + ((j)%7), (j)/7-3, (j)%7-3 }
__constant__ int4 JT[49] = {
    JT4(0),  JT4(1),  JT4(2),  JT4(3),  JT4(4),  JT4(5),  JT4(6),
    JT4(7),  JT4(8),  JT4(9),  JT4(10), JT4(11), JT4(12), JT4(13),
    JT4(14), JT4(15), JT4(16), JT4(17), JT4(18), JT4(19), JT4(20),
    JT4(21), JT4(22), JT4(23), JT4(24), JT4(25), JT4(26), JT4(27),
    JT4(28), JT4(29), JT4(30), JT4(31), JT4(32), JT4(33), JT4(34),
    JT4(35), JT4(36), JT4(37), JT4(38), JT4(39), JT4(40), JT4(41),
    JT4(42), JT4(43), JT4(44), JT4(45), JT4(46), JT4(47), JT4(48)
};

// FMA-pipe exp, input clamped at -80 (only hits weights <= e^-50 of max term).
__device__ __forceinline__ float fexp(float x)
{
    float y = fmaxf(x, -80.f) * 1.44269504f;
    float r = y + 12582912.f;
    int   n = __float_as_int(r) - 0x4B400000;
    float f = y - (r - 12582912.f);
    float p =              0.00961813f;
    p = __fmaf_rn(p, f,    0.05550411f);
    p = __fmaf_rn(p, f,    0.24022651f);
    p = __fmaf_rn(p, f,    0.69314718f);
    p = __fmaf_rn(p, f,    1.0f);
    return __int_as_float(__float_as_int(p) + (n << 23));
}

__global__ __launch_bounds__(NTHREADS, 2)
void attn_pk_kernel(const float* __restrict__ u,
                    const float* __restrict__ pan,
                    const float* __restrict__ Wphi,
                    const float* __restrict__ Wg,
                    float* __restrict__ out)
{
    extern __shared__ __align__(16) char smem_raw[];
    float4* phiA = (float4*)(smem_raw + OFF_PHIA);
    float4* phiB = (float4*)(smem_raw + OFF_PHIB);
    float4* gA   = (float4*)(smem_raw + OFF_GA);
    float4* gB   = (float4*)(smem_raw + OFF_GB);
    float*  Csb  = (float*)(smem_raw + OFF_CS);
    unsigned long long* wpk = (unsigned long long*)(smem_raw + OFF_WPK); // [64]
    float*  Hsb  = (float*)(smem_raw + OFF_HS);

    const int tid  = threadIdx.x;
    const int bimg = blockIdx.z;
    const int y0   = blockIdx.y * TY;
    const int x0   = blockIdx.x * TX;

    const float* panb = pan + (size_t)bimg * NCH * PL;
    const float* ub   = u   + (size_t)bimg * NCH * PL;

    // ---- prologue: issue input LDGs FIRST (in flight across the weight sync) ----
    const bool doPhi = (tid < NPHI);
    const int  gcell = (tid >= NPHI) ? (tid - NPHI)
                     : (tid < NG - NPIX ? tid + NPIX : -1);

    float pv[NCH], uv[NCH];
    if (doPhi) {
        int r = tid / PW, c = tid % PW;
        int yy = y0 - HP + r, xx = x0 - HP + c;
        bool in = ((unsigned)yy < IMG_H) && ((unsigned)xx < IMG_W);
        #pragma unroll
        for (int ch = 0; ch < NCH; ch++)
            pv[ch] = in ? panb[ch*PL + yy*IMG_W + xx] : 0.f;
    }
    if (gcell >= 0) {
        int r = gcell / GW, c = gcell % GW;
        int yy = y0 - HG + r, xx = x0 - HG + c;
        bool in = ((unsigned)yy < IMG_H) && ((unsigned)xx < IMG_W);
        #pragma unroll
        for (int ch = 0; ch < NCH; ch++)
            uv[ch] = in ? ub[ch*PL + yy*IMG_W + xx] : 0.f;
    }

    // packed weight pairs: wpk[ci*4+op] = (W[2op][ci], W[2op+1][ci])
    if (tid < 64) {
        const float* W = (tid < 32) ? Wphi : Wg;
        int t  = tid & 31;
        int ci = t >> 2, op = t & 3;
        float wlo = W[(2*op  )*NCH + ci];
        float whi = W[(2*op+1)*NCH + ci];
        unsigned long long wp; PACK2(wp, wlo, whi);
        wpk[tid] = wp;
    }
    __syncthreads();

    if (doPhi) {
        unsigned long long acc[4];
        #pragma unroll
        for (int ci = 0; ci < NCH; ci++) {
            unsigned long long pvx2; PACK2(pvx2, pv[ci], pv[ci]);
            #pragma unroll
            for (int op = 0; op < 4; op++) {
                if (ci == 0) { MUL2(acc[op], wpk[op], pvx2); }
                else         { FMA2(acc[op], wpk[ci*4+op], pvx2, acc[op]); }
            }
        }
        *(ulonglong2*)&phiA[tid] = make_ulonglong2(acc[0], acc[1]);
        *(ulonglong2*)&phiB[tid] = make_ulonglong2(acc[2], acc[3]);
    }
    if (gcell >= 0) {
        unsigned long long acc[4];
        #pragma unroll
        for (int ci = 0; ci < NCH; ci++) {
            unsigned long long uvx2; PACK2(uvx2, uv[ci], uv[ci]);
            #pragma unroll
            for (int op = 0; op < 4; op++) {
                if (ci == 0) { MUL2(acc[op], wpk[32 + op], uvx2); }
                else         { FMA2(acc[op], wpk[32 + ci*4+op], uvx2, acc[op]); }
            }
        }
        *(ulonglong2*)&gA[gcell] = make_ulonglong2(acc[0], acc[1]);
        *(ulonglong2*)&gB[gcell] = make_ulonglong2(acc[2], acc[3]);
    }
    __syncthreads();

    const int px    = tid & (NPIX-1);
    const int slice = tid >> 7;            // owns offsets j = slice + 4k
    const int bar   = slice + 1;
    const int ty = px / TX, tx = px % TX;
    const int gy = y0 + ty, gx = x0 + tx;

    // extra correlation positions: warps 0-1 of each slice (px < 52) — whole
    // warps skip the has1 branch, no predication cost in warps 2-3.
    const int p0    = px;
    const int cell0 = (p0/CW + 3) * PW + (p0%CW + 3);
    const bool has1 = (px < CN - NPIX);
    const int p1    = px + NPIX;
    const int cell1 = has1 ? (p1/CW + 3) * PW + (p1%CW + 3) : cell0;

    unsigned long long v0p0, v0p1, v0p2, v0p3, v1p0, v1p1, v1p2, v1p3;
    {
        ulonglong2 a = *(const ulonglong2*)&phiA[cell0];
        ulonglong2 b = *(const ulonglong2*)&phiB[cell0];
        v0p0 = a.x; v0p1 = a.y; v0p2 = b.x; v0p3 = b.y;
        ulonglong2 a1 = *(const ulonglong2*)&phiA[cell1];
        ulonglong2 b1 = *(const ulonglong2*)&phiB[cell1];
        v1p0 = a1.x; v1p1 = a1.y; v1p2 = b1.x; v1p3 = b1.y;
    }

    float* Cme = Csb + slice * (KMAX*CNP);
    float* Hme = Hsb + slice * (KMAX*HN);

    // ---- produce all C maps for this slice ----
    #pragma unroll
    for (int k = 0; k < KMAX; k++) {
        const int j = slice + 4*k;
        if (j < 49) {
            const int off = JT[j].x;
            {
                ulonglong2 wa = *(const ulonglong2*)&phiA[cell0 + off];
                ulonglong2 wb = *(const ulonglong2*)&phiB[cell0 + off];
                unsigned long long acc;
                MUL2(acc, v0p0, wa.x);
                FMA2(acc, v0p1, wa.y, acc);
                FMA2(acc, v0p2, wb.x, acc);
                FMA2(acc, v0p3, wb.y, acc);
                float lo, hi; UNPACK2(lo, hi, acc);
                Cme[k*CNP + p0] = lo + hi;
            }
            if (has1) {
                ulonglong2 wa = *(const ulonglong2*)&phiA[cell1 + off];
                ulonglong2 wb = *(const ulonglong2*)&phiB[cell1 + off];
                unsigned long long acc;
                MUL2(acc, v1p0, wa.x);
                FMA2(acc, v1p1, wa.y, acc);
                FMA2(acc, v1p2, wb.x, acc);
                FMA2(acc, v1p3, wb.y, acc);
                float lo, hi; UNPACK2(lo, hi, acc);
                Cme[k*CNP + p1] = lo + hi;
            }
        }
    }
    BARS(bar);     // slice-local: C produce -> H stage

    // ---- H stage: horizontal 3-sums, pairs of columns ----
    #pragma unroll
    for (int i = 0; i < 9; i++) {
        const int uu = px + 128*i;
        if (uu < HUNITS) {
            const int k  = uu / HPAIRS;
            const int pr = uu - k*HPAIRS;
            const int r  = pr >> 3;
            const int c0 = (pr & 7) << 1;
            const float2 a = *(const float2*)&Cme[k*CNP + r*CW + c0];
            const float2 b = *(const float2*)&Cme[k*CNP + r*CW + c0 + 2];
            float h0 = a.x + a.y + b.x;
            float h1 = a.y + b.x + b.y;
            *(float2*)&Hme[k*HN + r*HW + c0] = make_float2(h0, h1);
        }
    }
    __syncthreads();   // full: all slices need slice0's H (k=6 <-> j=24, delta=0)

    // ---- per-pixel shift b = self-logit ||theta_q||^2 (box-sum of C_0) ----
    float b;
    {
        const float* h0 = &Hsb[6*HN + ty*HW + tx];
        b = h0[0] + h0[HW] + h0[2*HW];
    }

    // ---- single fused pass: logit -> exp(l-b) -> accumulate ----
    const int gbase = ty * GW + tx;
    float S = 0.f;
    unsigned long long o01 = 0ULL, o23 = 0ULL, o45 = 0ULL, o67 = 0ULL;
    #pragma unroll
    for (int k = 0; k < KMAX; k++) {
        const int j = slice + 4*k;
        if (j < 49) {
            const int4 jt = JT[j];
            const float* hb = &Hme[k*HN + ty*HW + tx];
            float v = hb[0] + hb[HW] + hb[2*HW];
            const bool in = ((unsigned)(gy+jt.z) < IMG_H) && ((unsigned)(gx+jt.w) < IMG_W);
            float l = in ? v : 0.f;       // double-unfold: OOB logit exactly 0
            float e = fexp(l - b);
            S += e;
            unsigned long long e2; PACK2(e2, e, e);
            const int gi = gbase + jt.y;
            ulonglong2 g0 = *(const ulonglong2*)&gA[gi];
            ulonglong2 g1 = *(const ulonglong2*)&gB[gi];
            FMA2(o01, e2, g0.x, o01);
            FMA2(o23, e2, g0.y, o23);
            FMA2(o45, e2, g1.x, o45);
            FMA2(o67, e2, g1.y, o67);
        }
    }

    // ---- merge: plain sums across 4 slices (common shift b), packed scratch ----
    __syncthreads();                      // all slices done with Cs/Hs
    float* redS = Csb;                                  // [512] floats
    unsigned long long* redO = (unsigned long long*)(Csb + NTHREADS); // [4][512]
    redS[tid] = S;
    redO[0*NTHREADS + tid] = o01;
    redO[1*NTHREADS + tid] = o23;
    redO[2*NTHREADS + tid] = o45;
    redO[3*NTHREADS + tid] = o67;
    __syncthreads();

    {
        float St = redS[0*NPIX + px] + redS[1*NPIX + px]
                 + redS[2*NPIX + px] + redS[3*NPIX + px];
        float inv = 1.f / St;

        // slice s merges channel-pair s (o-plane s): 4 LDS.64 + 2 STG
        const unsigned long long* rp = redO + slice*NTHREADS + px;
        float a0, a1, t0, t1;
        UNPACK2(a0, a1, rp[0*NPIX]);
        UNPACK2(t0, t1, rp[1*NPIX]);  a0 += t0; a1 += t1;
        UNPACK2(t0, t1, rp[2*NPIX]);  a0 += t0; a1 += t1;
        UNPACK2(t0, t1, rp[3*NPIX]);  a0 += t0; a1 += t1;

        const int ch0 = 2*slice;
        float* ob = out + (size_t)bimg*NCH*PL + (size_t)gy*IMG_W + gx;
        ob[ch0*PL]     = a0 * inv;
        ob[(ch0+1)*PL] = a1 * inv;
    }
}

extern "C" void kernel_launch(void* const* d_in, const int* in_sizes, int n_in,
                              void* d_out, int out_size)
{
    const float* u    = (const float*)d_in[0];
    const float* pan  = (const float*)d_in[1];
    const float* Wphi = (const float*)d_in[2];
    const float* Wg   = (const float*)d_in[3];
    float* out = (float*)d_out;

    cudaFuncSetAttribute(attn_pk_kernel,
                         cudaFuncAttributeMaxDynamicSharedMemorySize, SMEM_TOTAL);

    dim3 grid(IMG_W / TX, IMG_H / TY, NB);   // (8, 16, 2) = 256 blocks
    dim3 block(NTHREADS);                     // 512
    attn_pk_kernel<<<grid, block, SMEM_TOTAL>>>(u, pan, Wphi, Wg, out);
}

// round 12
// speedup vs baseline: 1.0832x; 1.0789x over previous
#include <cuda_runtime.h>
#include <cuda_bf16.h>

// Problem constants (fixed by the dataset: b=2, c=8, h=w=128, P=3, Wn=7)
#define IMG_H 128
#define IMG_W 128
#define NCH 8
#define NB 2
#define PL (IMG_H*IMG_W)

// 16x16 tile, one CTA per SM (grid 128 <= 148 SMs), 4 slices x 256 px
#define TY 16
#define TX 16
#define NPIX (TY*TX)           // 256 pixels per tile
#define NSLICE 4
#define NTHREADS (NPIX*NSLICE) // 1024
#define HP 4                   // phi halo
#define HG 3                   // g halo
#define PH (TY + 2*HP)         // 24
#define PW (TX + 2*HP)         // 24
#define GH (TY + 2*HG)         // 22
#define GW (TX + 2*HG)         // 22
#define NPHI (PH*PW)           // 576
#define NG (GH*GW)             // 484

// Correlation map: tile dilated by 1 (patch radius)
#define CW 18
#define CHh 18
#define CN (CHh*CW)            // 324
#define CNP 328                // padded stride
#define KMAX 13                // maps per slice (slice 0: 13, others: 12)

// H map: horizontal 3-sums, 18 rows x 16 cols
#define HW 16
#define HN (CHh*HW)            // 288
#define HPAIRS (CHh*HW/2)      // 144
#define HUNITS (KMAX*HPAIRS)   // 1872

// ---- dynamic shared memory layout (bytes) ----
#define OFF_PHIA 0
#define OFF_PHIB (OFF_PHIA + NPHI*16)            // 9216
#define OFF_GA   (OFF_PHIB + NPHI*16)            // 18432
#define OFF_GB   (OFF_GA   + NG*16)              // 26176
#define OFF_CS   (OFF_GB   + NG*16)              // 33920
#define OFF_WPK  (OFF_CS   + NSLICE*KMAX*CNP*4)  // 102144
#define OFF_HS   (OFF_WPK  + 512)                // 102656
#define SMEM_TOTAL (OFF_HS + NSLICE*KMAX*HN*4)   // 162560

#define BARS(id) asm volatile("bar.sync %0, %1;" :: "r"(id), "r"(256) : "memory")

#define MUL2(out, a, b) \
    asm("mul.rn.f32x2 %0, %1, %2;" : "=l"(out) : "l"(a), "l"(b))
#define FMA2(out, a, b, c) \
    asm("fma.rn.f32x2 %0, %1, %2, %3;" : "=l"(out) : "l"(a), "l"(b), "l"(c))
#define PACK2(out, lo, hi) \
    asm("mov.b64 %0, {%1, %2};" : "=l"(out) : "f"(lo), "f"(hi))
#define UNPACK2(lo, hi, in) \
    asm("mov.b64 {%0, %1}, %2;" : "=f"(lo), "=f"(hi) : "l"(in))

// compile-time per-offset table: {phi-desc offset, g offset, dy, dx}
#define JT4(j) { ((j)/7-3)*PW + ((j)%7-3), ((j)/7)*GW + ((j)%7), (j)/7-3, (j)%7-3 }
__constant__ int4 JT[49] = {
    JT4(0),  JT4(1),  JT4(2),  JT4(3),  JT4(4),  JT4(5),  JT4(6),
    JT4(7),  JT4(8),  JT4(9),  JT4(10), JT4(11), JT4(12), JT4(13),
    JT4(14), JT4(15), JT4(16), JT4(17), JT4(18), JT4(19), JT4(20),
    JT4(21), JT4(22), JT4(23), JT4(24), JT4(25), JT4(26), JT4(27),
    JT4(28), JT4(29), JT4(30), JT4(31), JT4(32), JT4(33), JT4(34),
    JT4(35), JT4(36), JT4(37), JT4(38), JT4(39), JT4(40), JT4(41),
    JT4(42), JT4(43), JT4(44), JT4(45), JT4(46), JT4(47), JT4(48)
};

// FMA-pipe exp, input clamped at -80 (only hits weights <= e^-50 of max term).
__device__ __forceinline__ float fexp(float x)
{
    float y = fmaxf(x, -80.f) * 1.44269504f;
    float r = y + 12582912.f;
    int   n = __float_as_int(r) - 0x4B400000;
    float f = y - (r - 12582912.f);
    float p =              0.00961813f;
    p = __fmaf_rn(p, f,    0.05550411f);
    p = __fmaf_rn(p, f,    0.24022651f);
    p = __fmaf_rn(p, f,    0.69314718f);
    p = __fmaf_rn(p, f,    1.0f);
    return __int_as_float(__float_as_int(p) + (n << 23));
}

__global__ __launch_bounds__(NTHREADS, 1)
void attn_big_kernel(const float* __restrict__ u,
                     const float* __restrict__ pan,
                     const float* __restrict__ Wphi,
                     const float* __restrict__ Wg,
                     float* __restrict__ out)
{
    extern __shared__ __align__(16) char smem_raw[];
    float4* phiA = (float4*)(smem_raw + OFF_PHIA);
    float4* phiB = (float4*)(smem_raw + OFF_PHIB);
    float4* gA   = (float4*)(smem_raw + OFF_GA);
    float4* gB   = (float4*)(smem_raw + OFF_GB);
    float*  Csb  = (float*)(smem_raw + OFF_CS);
    unsigned long long* wpk = (unsigned long long*)(smem_raw + OFF_WPK); // [64]
    float*  Hsb  = (float*)(smem_raw + OFF_HS);

    const int tid  = threadIdx.x;
    const int bimg = blockIdx.z;
    const int y0   = blockIdx.y * TY;
    const int x0   = blockIdx.x * TX;

    const float* panb = pan + (size_t)bimg * NCH * PL;
    const float* ub   = u   + (size_t)bimg * NCH * PL;

    // ---- prologue: issue input LDGs FIRST (in flight across the weight sync) ----
    // 576 phi units + 484 g units over 1024 threads (36 threads do 2 units)
    const bool doPhi = (tid < NPHI);
    const int  gcell = (tid >= NPHI) ? (tid - NPHI)
                     : (tid < NG - (NTHREADS - NPHI) ? tid + (NTHREADS - NPHI) : -1);

    float pv[NCH], uv[NCH];
    if (doPhi) {
        int r = tid / PW, c = tid % PW;
        int yy = y0 - HP + r, xx = x0 - HP + c;
        bool in = ((unsigned)yy < IMG_H) && ((unsigned)xx < IMG_W);
        #pragma unroll
        for (int ch = 0; ch < NCH; ch++)
            pv[ch] = in ? panb[ch*PL + yy*IMG_W + xx] : 0.f;
    }
    if (gcell >= 0) {
        int r = gcell / GW, c = gcell % GW;
        int yy = y0 - HG + r, xx = x0 - HG + c;
        bool in = ((unsigned)yy < IMG_H) && ((unsigned)xx < IMG_W);
        #pragma unroll
        for (int ch = 0; ch < NCH; ch++)
            uv[ch] = in ? ub[ch*PL + yy*IMG_W + xx] : 0.f;
    }

    // packed weight pairs: wpk[ci*4+op] = (W[2op][ci], W[2op+1][ci])
    if (tid < 64) {
        const float* W = (tid < 32) ? Wphi : Wg;
        int t  = tid & 31;
        int ci = t >> 2, op = t & 3;
        float wlo = W[(2*op  )*NCH + ci];
        float whi = W[(2*op+1)*NCH + ci];
        unsigned long long wp; PACK2(wp, wlo, whi);
        wpk[tid] = wp;
    }
    __syncthreads();

    if (doPhi) {
        unsigned long long acc[4];
        #pragma unroll
        for (int ci = 0; ci < NCH; ci++) {
            unsigned long long pvx2; PACK2(pvx2, pv[ci], pv[ci]);
            #pragma unroll
            for (int op = 0; op < 4; op++) {
                if (ci == 0) { MUL2(acc[op], wpk[op], pvx2); }
                else         { FMA2(acc[op], wpk[ci*4+op], pvx2, acc[op]); }
            }
        }
        *(ulonglong2*)&phiA[tid] = make_ulonglong2(acc[0], acc[1]);
        *(ulonglong2*)&phiB[tid] = make_ulonglong2(acc[2], acc[3]);
    }
    if (gcell >= 0) {
        unsigned long long acc[4];
        #pragma unroll
        for (int ci = 0; ci < NCH; ci++) {
            unsigned long long uvx2; PACK2(uvx2, uv[ci], uv[ci]);
            #pragma unroll
            for (int op = 0; op < 4; op++) {
                if (ci == 0) { MUL2(acc[op], wpk[32 + op], uvx2); }
                else         { FMA2(acc[op], wpk[32 + ci*4+op], uvx2, acc[op]); }
            }
        }
        *(ulonglong2*)&gA[gcell] = make_ulonglong2(acc[0], acc[1]);
        *(ulonglong2*)&gB[gcell] = make_ulonglong2(acc[2], acc[3]);
    }
    __syncthreads();

    const int px    = tid & (NPIX-1);      // pixel within tile (0..255)
    const int slice = tid >> 8;            // owns offsets j = slice + 4k
    const int bar   = slice + 1;
    const int ty = px >> 4, tx = px & 15;
    const int gy = y0 + ty, gx = x0 + tx;

    // correlation positions: primary = px; extras (324-256=68) in low warps
    const int p0    = px;
    const int cell0 = (p0/CW + 3) * PW + (p0%CW + 3);
    const bool has1 = (px < CN - NPIX);    // px < 68
    const int p1    = px + NPIX;
    const int cell1 = has1 ? (p1/CW + 3) * PW + (p1%CW + 3) : cell0;

    unsigned long long v0p0, v0p1, v0p2, v0p3, v1p0, v1p1, v1p2, v1p3;
    {
        ulonglong2 a = *(const ulonglong2*)&phiA[cell0];
        ulonglong2 b = *(const ulonglong2*)&phiB[cell0];
        v0p0 = a.x; v0p1 = a.y; v0p2 = b.x; v0p3 = b.y;
        ulonglong2 a1 = *(const ulonglong2*)&phiA[cell1];
        ulonglong2 b1 = *(const ulonglong2*)&phiB[cell1];
        v1p0 = a1.x; v1p1 = a1.y; v1p2 = b1.x; v1p3 = b1.y;
    }

    float* Cme = Csb + slice * (KMAX*CNP);
    float* Hme = Hsb + slice * (KMAX*HN);

    // ---- produce all C maps for this slice ----
    #pragma unroll
    for (int k = 0; k < KMAX; k++) {
        const int j = slice + 4*k;
        if (j < 49) {
            const int off = JT[j].x;
            {
                ulonglong2 wa = *(const ulonglong2*)&phiA[cell0 + off];
                ulonglong2 wb = *(const ulonglong2*)&phiB[cell0 + off];
                unsigned long long acc;
                MUL2(acc, v0p0, wa.x);
                FMA2(acc, v0p1, wa.y, acc);
                FMA2(acc, v0p2, wb.x, acc);
                FMA2(acc, v0p3, wb.y, acc);
                float lo, hi; UNPACK2(lo, hi, acc);
                Cme[k*CNP + p0] = lo + hi;
            }
            if (has1) {
                ulonglong2 wa = *(const ulonglong2*)&phiA[cell1 + off];
                ulonglong2 wb = *(const ulonglong2*)&phiB[cell1 + off];
                unsigned long long acc;
                MUL2(acc, v1p0, wa.x);
                FMA2(acc, v1p1, wa.y, acc);
                FMA2(acc, v1p2, wb.x, acc);
                FMA2(acc, v1p3, wb.y, acc);
                float lo, hi; UNPACK2(lo, hi, acc);
                Cme[k*CNP + p1] = lo + hi;
            }
        }
    }
    BARS(bar);     // slice-local (256 threads): C produce -> H stage

    // ---- H stage: horizontal 3-sums, pairs of columns (1872 units/slice) ----
    #pragma unroll
    for (int i = 0; i < 8; i++) {
        const int uu = px + NPIX*i;
        if (uu < HUNITS) {
            const int k  = uu / HPAIRS;
            const int pr = uu - k*HPAIRS;
            const int r  = pr >> 3;
            const int c0 = (pr & 7) << 1;
            const float2 a = *(const float2*)&Cme[k*CNP + r*CW + c0];
            const float2 b = *(const float2*)&Cme[k*CNP + r*CW + c0 + 2];
            float h0 = a.x + a.y + b.x;
            float h1 = a.y + b.x + b.y;
            *(float2*)&Hme[k*HN + r*HW + c0] = make_float2(h0, h1);
        }
    }
    __syncthreads();   // full: all slices need slice0's H (k=6 <-> j=24, delta=0)

    // ---- per-pixel shift b = self-logit ||theta_q||^2 (box-sum of C_0) ----
    float b;
    {
        const float* h0 = &Hsb[6*HN + ty*HW + tx];
        b = h0[0] + h0[HW] + h0[2*HW];
    }

    // ---- single fused pass: logit -> exp(l-b) -> accumulate ----
    const int gbase = ty * GW + tx;
    float S = 0.f;
    unsigned long long o01 = 0ULL, o23 = 0ULL, o45 = 0ULL, o67 = 0ULL;
    #pragma unroll
    for (int k = 0; k < KMAX; k++) {
        const int j = slice + 4*k;
        if (j < 49) {
            const int4 jt = JT[j];
            const float* hb = &Hme[k*HN + ty*HW + tx];
            float v = hb[0] + hb[HW] + hb[2*HW];
            const bool in = ((unsigned)(gy+jt.z) < IMG_H) && ((unsigned)(gx+jt.w) < IMG_W);
            float l = in ? v : 0.f;       // double-unfold: OOB logit exactly 0
            float e = fexp(l - b);
            S += e;
            unsigned long long e2; PACK2(e2, e, e);
            const int gi = gbase + jt.y;
            ulonglong2 g0 = *(const ulonglong2*)&gA[gi];
            ulonglong2 g1 = *(const ulonglong2*)&gB[gi];
            FMA2(o01, e2, g0.x, o01);
            FMA2(o23, e2, g0.y, o23);
            FMA2(o45, e2, g1.x, o45);
            FMA2(o67, e2, g1.y, o67);
        }
    }

    // ---- merge: plain sums across 4 slices (common shift b), packed scratch ----
    __syncthreads();                      // all slices done with Cs/Hs
    float* redS = Csb;                                  // [1024] floats
    unsigned long long* redO = (unsigned long long*)(Csb + NTHREADS); // [4][1024]
    redS[tid] = S;
    redO[0*NTHREADS + tid] = o01;
    redO[1*NTHREADS + tid] = o23;
    redO[2*NTHREADS + tid] = o45;
    redO[3*NTHREADS + tid] = o67;
    __syncthreads();

    {
        float St = redS[0*NPIX + px] + redS[1*NPIX + px]
                 + redS[2*NPIX + px] + redS[3*NPIX + px];
        float inv = 1.f / St;

        // slice s merges channel-pair s (o-plane s): 4 LDS.64 + 2 STG
        const unsigned long long* rp = redO + slice*NTHREADS + px;
        float a0, a1, t0, t1;
        UNPACK2(a0, a1, rp[0*NPIX]);
        UNPACK2(t0, t1, rp[1*NPIX]);  a0 += t0; a1 += t1;
        UNPACK2(t0, t1, rp[2*NPIX]);  a0 += t0; a1 += t1;
        UNPACK2(t0, t1, rp[3*NPIX]);  a0 += t0; a1 += t1;

        const int ch0 = 2*slice;
        float* ob = out + (size_t)bimg*NCH*PL + (size_t)gy*IMG_W + gx;
        ob[ch0*PL]     = a0 * inv;
        ob[(ch0+1)*PL] = a1 * inv;
    }
}

extern "C" void kernel_launch(void* const* d_in, const int* in_sizes, int n_in,
                              void* d_out, int out_size)
{
    const float* u    = (const float*)d_in[0];
    const float* pan  = (const float*)d_in[1];
    const float* Wphi = (const float*)d_in[2];
    const float* Wg   = (const float*)d_in[3];
    float* out = (float*)d_out;

    cudaFuncSetAttribute(attn_big_kernel,
                         cudaFuncAttributeMaxDynamicSharedMemorySize, SMEM_TOTAL);

    dim3 grid(IMG_W / TX, IMG_H / TY, NB);   // (8, 8, 2) = 128 blocks, 1 per SM
    dim3 block(NTHREADS);                     // 1024
    attn_big_kernel<<<grid, block, SMEM_TOTAL>>>(u, pan, Wphi, Wg, out);
}